// round 8
// baseline (speedup 1.0000x reference)
#include <cuda_runtime.h>
#include <math.h>

#define BATCH 512
#define LSEQ  100
#define NINPUT 3
#define HDIM  256
#define G3    768
#define DSH   10
#define WINW  5
#define MSEQ  95          // LSEQ - WINW
#define TB    4           // batch samples per recurrent block
#define NC    16          // weight slices cached in SMEM (of 64, bf16)

#define BL    (BATCH*LSEQ)      // 51200
#define BM95  (BATCH*MSEQ)      // 48640

typedef unsigned long long u64;

// ---------------- scratch (static device memory; no allocations) ----------
__device__ float  g_xw1 [2*BL*G3];          // layer-1 gate inputs, per GRU
__device__ float  g_h1  [2*BL*HDIM];        // layer-0 outputs
__device__ float  g_out [2*BL*HDIM];        // layer-1 outputs (out1/out2)
__device__ float  g_q   [2*BL];
__device__ float  g_e   [2*BL];
__device__ float  g_cat [2*BM95*2*HDIM];    // [c, out_shift] concat for FC
__device__ float  g_fused[2*BM95*HDIM];     // FC output
__device__ uint2  g_wB  [4*64*G3];          // Whh as packed bf16 quads
// g_wB layout: [slot][kk 0..63][gatecol 0..767], quad = 4 k-values (bf16)
// slots: 0=r1_Whh0 1=r2_Whh0 2=r1_Whh1 3=r2_Whh1

__device__ __forceinline__ float sigf(float x) { return 1.f / (1.f + __expf(-x)); }

// packed dual-fp32 FMA: acc.{lo,hi} += a.{lo,hi} * b.{lo,hi}
__device__ __forceinline__ void fma2(u64& acc, u64 a, u64 b) {
    asm("fma.rn.f32x2 %0, %1, %2, %0;" : "+l"(acc) : "l"(a), "l"(b));
}
__device__ __forceinline__ u64 splat2(float x) {
    u64 r; asm("mov.b64 %0, {%1, %1};" : "=l"(r) : "f"(x)); return r;
}
__device__ __forceinline__ float sum2(u64 v) {
    float lo, hi; asm("mov.b64 {%0, %1}, %2;" : "=f"(lo), "=f"(hi) : "l"(v));
    return lo + hi;
}
// round-to-nearest-even fp32 -> bf16 bits
__device__ __forceinline__ unsigned bfr(float f) {
    unsigned u = __float_as_uint(f);
    return (u + 0x7FFFu + ((u >> 16) & 1u)) >> 16;
}
// expand packed bf16 quad -> two f32x2 operands (PRMT: bf16<<16 == fp32)
__device__ __forceinline__ void expand(uint2 p, u64& a, u64& b) {
    unsigned f0, f1, f2, f3;
    asm("prmt.b32 %0, %1, 0, 0x1044;" : "=r"(f0) : "r"(p.x));
    asm("prmt.b32 %0, %1, 0, 0x3244;" : "=r"(f1) : "r"(p.x));
    asm("prmt.b32 %0, %1, 0, 0x1044;" : "=r"(f2) : "r"(p.y));
    asm("prmt.b32 %0, %1, 0, 0x3244;" : "=r"(f3) : "r"(p.y));
    asm("mov.b64 %0, {%1, %2};" : "=l"(a) : "r"(f0), "r"(f1));
    asm("mov.b64 %0, {%1, %2};" : "=l"(b) : "r"(f2), "r"(f3));
}

// ---------------- weight prep: W[g][k] -> bf16 quads [kk][g] ---------------
__global__ void k_prep(const float* __restrict__ w0, const float* __restrict__ w1,
                       const float* __restrict__ w2, const float* __restrict__ w3)
{
    int idx = blockIdx.x * blockDim.x + threadIdx.x;
    if (idx >= 4 * 64 * G3) return;
    int g  = idx % G3;
    int kk = (idx / G3) % 64;
    int m  = idx / (G3 * 64);
    const float* W = (m == 0) ? w0 : (m == 1) ? w1 : (m == 2) ? w2 : w3;
    const float* p = W + g * HDIM + 4 * kk;
    uint2 q;
    q.x = bfr(p[0]) | (bfr(p[1]) << 16);
    q.y = bfr(p[2]) | (bfr(p[3]) << 16);
    g_wB[idx] = q;
}

// ---------------- GRU recurrence ------------------------------------------
// 256 threads, TB=4, full-k per thread, 2 CTAs/SM (tails overlap).
// Double-buffered h state -> ONE barrier per step. bf16 weights:
// NC slices in SMEM, remainder streamed from gmem with depth-2 prefetch.
// FUSE=1: layer 0 — input projection (NINPUT=3) fused, weights in registers.
// FUSE=0: layer 1 — precomputed gate inputs, pipelined one step ahead.
template<int FUSE>
__global__ void __launch_bounds__(256, 2)
k_rec(const float* __restrict__ xw_base, const float* __restrict__ xin,
      const float* __restrict__ Wih_0, const float* __restrict__ Wih_1,
      const float* __restrict__ bih_0, const float* __restrict__ bih_1,
      int wslot,
      const float* __restrict__ bhh_0, const float* __restrict__ bhh_1,
      float* __restrict__ hout_base)
{
    int r  = blockIdx.y;
    int j  = threadIdx.x;                 // gate/hidden column 0..255
    int b0 = blockIdx.x * TB;
    const float* bhh    = r ? bhh_1 : bhh_0;
    const uint2* WBbase = g_wB + (size_t)(wslot + r) * (64 * G3);
    const uint2* WgB    = WBbase + NC * G3;     // streamed slices NC..63
    const float* xw     = xw_base ? (xw_base + (size_t)r * BL * G3) : (const float*)0;
    float*       hout   = hout_base + (size_t)r * BL * HDIM;

    // dynamic SMEM carve: hs (double-buffered) | Wc (bf16 slice cache)
    extern __shared__ __align__(16) char dsm[];
    float* hs = (float*)dsm;                    // [2][TB][HDIM]
    uint2* Wc = (uint2*)(hs + 2 * TB * HDIM);   // [NC][G3]

    // one-time: stage first NC bf16 slices into SMEM
    for (int idx = j; idx < NC * G3; idx += 256) Wc[idx] = WBbase[idx];

    // fused input-projection weights (layer 0)
    float wx[9], bx[3];
    if (FUSE) {
        const float* Wih = r ? Wih_1 : Wih_0;
        const float* bih = r ? bih_1 : bih_0;
#pragma unroll
        for (int g = 0; g < 3; g++) {
            wx[g*3+0] = Wih[(j + g*HDIM)*3 + 0];
            wx[g*3+1] = Wih[(j + g*HDIM)*3 + 1];
            wx[g*3+2] = Wih[(j + g*HDIM)*3 + 2];
            bx[g]     = bih[j + g*HDIM];
        }
    }

#pragma unroll
    for (int i = 0; i < TB; i++) hs[i * HDIM + j] = 0.f;   // buffer 0
    float bhr = bhh[j], bhz = bhh[j + HDIM], bhn = bhh[j + 2*HDIM];

    // prologue: pipeline registers hold step-0 gate inputs
    float xg[3*TB];
    if (FUSE) {
#pragma unroll
        for (int i = 0; i < TB; i++) {
            size_t base = ((size_t)(b0 + i) * LSEQ + 0) * NINPUT;
            xg[i*3+0] = xin[base+0]; xg[i*3+1] = xin[base+1]; xg[i*3+2] = xin[base+2];
        }
    } else {
#pragma unroll
        for (int i = 0; i < TB; i++) {
            size_t base = ((size_t)(b0 + i) * LSEQ + 0) * G3;
            xg[i*3+0] = xw[base + j];
            xg[i*3+1] = xw[base + HDIM + j];
            xg[i*3+2] = xw[base + 2*HDIM + j];
        }
    }
    __syncthreads();

    for (int t = 0; t < LSEQ; t++) {
        const float* hr = hs + (t & 1) * TB * HDIM;       // read buffer
        float*       hw = hs + ((t + 1) & 1) * TB * HDIM; // write buffer

        u64 ar[TB], az[TB], an[TB];
#pragma unroll
        for (int i = 0; i < TB; i++) { ar[i]=0ull; az[i]=0ull; an[i]=0ull; }

        // ---- phase 1: SMEM-cached bf16 slices (kk 0..NC-1) ----
#pragma unroll 4
        for (int kk = 0; kk < NC; kk++) {
            uint2 q0 = Wc[kk*G3 + j];
            uint2 q1 = Wc[kk*G3 + HDIM + j];
            uint2 q2 = Wc[kk*G3 + 2*HDIM + j];
            u64 w0x, w0y, w1x, w1y, w2x, w2y;
            expand(q0, w0x, w0y); expand(q1, w1x, w1y); expand(q2, w2x, w2y);
#pragma unroll
            for (int i = 0; i < TB; i++) {
                ulonglong2 h2 = *(const ulonglong2*)&hr[i*HDIM + kk*4];
                fma2(ar[i], w0x, h2.x); fma2(ar[i], w0y, h2.y);
                fma2(az[i], w1x, h2.x); fma2(az[i], w1y, h2.y);
                fma2(an[i], w2x, h2.x); fma2(an[i], w2y, h2.y);
            }
        }

        // ---- phase 2: gmem bf16 slices (kk NC..63), prefetch depth 2 ----
        {
            uint2 p0[2], p1[2], p2[2];
#pragma unroll
            for (int d = 0; d < 2; d++) {
                p0[d] = WgB[d*G3 + j];
                p1[d] = WgB[d*G3 + HDIM + j];
                p2[d] = WgB[d*G3 + 2*HDIM + j];
            }
#pragma unroll 4
            for (int kk = NC; kk < 64; kk++) {
                int d = kk - NC;
                int s = d & 1;
                uint2 q0 = p0[s], q1 = p1[s], q2 = p2[s];
                if (d + 2 < 64 - NC) {
                    p0[s] = WgB[(d+2)*G3 + j];
                    p1[s] = WgB[(d+2)*G3 + HDIM + j];
                    p2[s] = WgB[(d+2)*G3 + 2*HDIM + j];
                }
                u64 w0x, w0y, w1x, w1y, w2x, w2y;
                expand(q0, w0x, w0y); expand(q1, w1x, w1y); expand(q2, w2x, w2y);
#pragma unroll
                for (int i = 0; i < TB; i++) {
                    ulonglong2 h2 = *(const ulonglong2*)&hr[i*HDIM + kk*4];
                    fma2(ar[i], w0x, h2.x); fma2(ar[i], w0y, h2.y);
                    fma2(az[i], w1x, h2.x); fma2(az[i], w1y, h2.y);
                    fma2(an[i], w2x, h2.x); fma2(an[i], w2y, h2.y);
                }
            }
        }

        // ---- pointwise update (writes the OTHER h buffer; one bar/step) ----
#pragma unroll
        for (int i = 0; i < TB; i++) {
            float gr, gz, gn;
            if (FUSE) {
                float x0 = xg[i*3+0], x1 = xg[i*3+1], x2 = xg[i*3+2];
                gr = bx[0] + x0*wx[0] + x1*wx[1] + x2*wx[2];
                gz = bx[1] + x0*wx[3] + x1*wx[4] + x2*wx[5];
                gn = bx[2] + x0*wx[6] + x1*wx[7] + x2*wx[8];
            } else {
                gr = xg[i*3+0]; gz = xg[i*3+1]; gn = xg[i*3+2];
            }
            float rg = sigf(gr + sum2(ar[i]) + bhr);
            float zg = sigf(gz + sum2(az[i]) + bhz);
            float ng = tanhf(gn + rg * (sum2(an[i]) + bhn));
            float hn = (1.f - zg) * ng + zg * hr[i*HDIM + j];
            hw[i*HDIM + j] = hn;
            hout[((size_t)(b0 + i) * LSEQ + t) * HDIM + j] = hn;
        }
        // prefetch next step's gate inputs
        if (t + 1 < LSEQ) {
            if (FUSE) {
#pragma unroll
                for (int i = 0; i < TB; i++) {
                    size_t base = ((size_t)(b0 + i) * LSEQ + (t+1)) * NINPUT;
                    xg[i*3+0] = xin[base+0]; xg[i*3+1] = xin[base+1]; xg[i*3+2] = xin[base+2];
                }
            } else {
#pragma unroll
                for (int i = 0; i < TB; i++) {
                    size_t base = ((size_t)(b0 + i) * LSEQ + (t+1)) * G3;
                    xg[i*3+0] = xw[base + j];
                    xg[i*3+1] = xw[base + HDIM + j];
                    xg[i*3+2] = xw[base + 2*HDIM + j];
                }
            }
        }
        __syncthreads();
    }
}

#define REC_SMEM (2*TB*HDIM*4 + NC*G3*8)

// ---------------- SGEMM: C[M,N] = A[M,K] @ B[N,K].T + bias ----------------
// 128x128 block tile, 256 threads, 8x8 per thread (f32x2), double-buffered.
__global__ void __launch_bounds__(256, 2)
k_gemm(const float* __restrict__ A, size_t strideAz,
       const float* __restrict__ B0, const float* __restrict__ B1,
       const float* __restrict__ bias0, const float* __restrict__ bias1,
       float* __restrict__ C, size_t strideCz,
       int N, int K)
{
    int z = blockIdx.z;
    const float* Az   = A + (size_t)z * strideAz;
    const float* Bw   = z ? B1 : B0;
    const float* bias = z ? bias1 : bias0;
    float*       Cz   = C + (size_t)z * strideCz;

    __shared__ __align__(16) float As[2][8][128];
    __shared__ __align__(16) float Bs[2][8][128];

    int bm = blockIdx.y * 128;
    int bn = blockIdx.x * 128;
    int tid = threadIdx.x;

    int lrow = tid >> 1;
    int lk   = (tid & 1) * 4;
    int tm = (tid >> 4) * 8;
    int tn = (tid & 15) * 8;

    u64 acc[4][8];
#pragma unroll
    for (int p = 0; p < 4; p++)
#pragma unroll
        for (int n = 0; n < 8; n++) acc[p][n] = 0ull;

    const int KT = K >> 3;

    float4 a4 = *(const float4*)&Az[(size_t)(bm + lrow) * K + lk];
    float4 b4 = *(const float4*)&Bw[(size_t)(bn + lrow) * K + lk];
    As[0][lk+0][lrow] = a4.x; As[0][lk+1][lrow] = a4.y;
    As[0][lk+2][lrow] = a4.z; As[0][lk+3][lrow] = a4.w;
    Bs[0][lk+0][lrow] = b4.x; Bs[0][lk+1][lrow] = b4.y;
    Bs[0][lk+2][lrow] = b4.z; Bs[0][lk+3][lrow] = b4.w;
    __syncthreads();

    for (int kt = 0; kt < KT; kt++) {
        int cur = kt & 1;
        if (kt + 1 < KT) {
            int k0 = (kt + 1) * 8;
            a4 = *(const float4*)&Az[(size_t)(bm + lrow) * K + k0 + lk];
            b4 = *(const float4*)&Bw[(size_t)(bn + lrow) * K + k0 + lk];
        }
#pragma unroll
        for (int k = 0; k < 8; k++) {
            ulonglong2 a01 = *(const ulonglong2*)&As[cur][k][tm];
            ulonglong2 a23 = *(const ulonglong2*)&As[cur][k][tm+4];
            float4 bv0 = *(const float4*)&Bs[cur][k][tn];
            float4 bv1 = *(const float4*)&Bs[cur][k][tn+4];
            u64 ap[4] = { a01.x, a01.y, a23.x, a23.y };
            u64 bs[8] = { splat2(bv0.x), splat2(bv0.y), splat2(bv0.z), splat2(bv0.w),
                          splat2(bv1.x), splat2(bv1.y), splat2(bv1.z), splat2(bv1.w) };
#pragma unroll
            for (int p = 0; p < 4; p++)
#pragma unroll
                for (int n = 0; n < 8; n++)
                    fma2(acc[p][n], ap[p], bs[n]);
        }
        if (kt + 1 < KT) {
            int nxt = cur ^ 1;
            As[nxt][lk+0][lrow] = a4.x; As[nxt][lk+1][lrow] = a4.y;
            As[nxt][lk+2][lrow] = a4.z; As[nxt][lk+3][lrow] = a4.w;
            Bs[nxt][lk+0][lrow] = b4.x; Bs[nxt][lk+1][lrow] = b4.y;
            Bs[nxt][lk+2][lrow] = b4.z; Bs[nxt][lk+3][lrow] = b4.w;
        }
        __syncthreads();
    }

    float bv[8];
#pragma unroll
    for (int n = 0; n < 8; n++) bv[n] = bias[bn + tn + n];
#pragma unroll
    for (int p = 0; p < 4; p++) {
        float r0[8], r1[8];
#pragma unroll
        for (int n = 0; n < 8; n++) {
            float lo, hi;
            asm("mov.b64 {%0, %1}, %2;" : "=f"(lo), "=f"(hi) : "l"(acc[p][n]));
            r0[n] = lo + bv[n]; r1[n] = hi + bv[n];
        }
        size_t row0 = (size_t)(bm + tm + 2*p) * N + bn + tn;
        size_t row1 = row0 + N;
        *(float4*)&Cz[row0]     = make_float4(r0[0], r0[1], r0[2], r0[3]);
        *(float4*)&Cz[row0 + 4] = make_float4(r0[4], r0[5], r0[6], r0[7]);
        *(float4*)&Cz[row1]     = make_float4(r1[0], r1[1], r1[2], r1[3]);
        *(float4*)&Cz[row1 + 4] = make_float4(r1[4], r1[5], r1[6], r1[7]);
    }
}

// ---------------- q = out@aw[:H], e = out@aw[H:] (warp per (b,l)) ----------
__global__ void k_qe(const float* __restrict__ attn_w)
{
    int r    = blockIdx.y;
    int w    = blockIdx.x * 8 + (threadIdx.x >> 5);
    int lane = threadIdx.x & 31;
    const float* o = g_out + ((size_t)r * BL + w) * HDIM;
    float q = 0.f, e = 0.f;
#pragma unroll
    for (int h = lane * 8; h < lane * 8 + 8; h += 4) {
        float4 ov = *(const float4*)&o[h];
        float4 a1 = *(const float4*)&attn_w[h];
        float4 a2 = *(const float4*)&attn_w[HDIM + h];
        q += ov.x*a1.x + ov.y*a1.y + ov.z*a1.z + ov.w*a1.w;
        e += ov.x*a2.x + ov.y*a2.y + ov.z*a2.z + ov.w*a2.w;
    }
#pragma unroll
    for (int off = 16; off; off >>= 1) {
        q += __shfl_down_sync(0xffffffffu, q, off);
        e += __shfl_down_sync(0xffffffffu, e, off);
    }
    if (lane == 0) { g_q[r * BL + w] = q; g_e[r * BL + w] = e; }
}

// ---------------- windowed attention + concat for FC ----------------------
__global__ void k_attn()
{
    int r    = blockIdx.y;
    int bl95 = blockIdx.x;
    int b    = bl95 / MSEQ, l = bl95 % MSEQ;
    int h    = threadIdx.x;

    const float* qrow = g_q + r * BL + b * LSEQ;
    const float* erow = g_e + r * BL + b * LSEQ;
    float qv = qrow[l + WINW];
    float s[WINW];
    float mx = -1e30f;
#pragma unroll
    for (int k = 0; k < WINW; k++) { s[k] = qv + erow[l + k]; mx = fmaxf(mx, s[k]); }
    float sum = 0.f;
#pragma unroll
    for (int k = 0; k < WINW; k++) { s[k] = __expf(s[k] - mx); sum += s[k]; }
    float inv = 1.f / sum;

    const float* o = g_out + ((size_t)r * BL + b * LSEQ + l) * HDIM;
    float c = 0.f;
#pragma unroll
    for (int k = 0; k < WINW; k++) c += s[k] * inv * o[k * HDIM + h];

    size_t m = (size_t)r * BM95 + bl95;
    g_cat[m * (2*HDIM) + h]        = c;
    g_cat[m * (2*HDIM) + HDIM + h] = o[WINW * HDIM + h];
}

// ---------------- final head: concat(rnn1[b,l], rnn2[b,min(l+D,99)]) ------
__global__ void k_final(const float* __restrict__ outW, const float* __restrict__ outb,
                        float* __restrict__ out)
{
    int w    = blockIdx.x * 8 + (threadIdx.x >> 5);
    int lane = threadIdx.x & 31;
    int b = w / LSEQ, l = w % LSEQ;

    const float* A1 = (l < WINW)
        ? (g_out   + ((size_t)(b * LSEQ + l)) * HDIM)
        : (g_fused + ((size_t)(b * MSEQ + l - WINW)) * HDIM);
    int lidx = min(l + DSH, LSEQ - 1);
    const float* A2 = (lidx < WINW)
        ? (g_out   + ((size_t)BL + b * LSEQ + lidx) * HDIM)
        : (g_fused + ((size_t)BM95 + b * MSEQ + lidx - WINW) * HDIM);

    float acc = 0.f;
#pragma unroll
    for (int h = lane * 8; h < lane * 8 + 8; h += 4) {
        float4 a  = *(const float4*)&A1[h];
        float4 w1 = *(const float4*)&outW[h];
        acc += a.x*w1.x + a.y*w1.y + a.z*w1.z + a.w*w1.w;
        float4 a2 = *(const float4*)&A2[h];
        float4 w2 = *(const float4*)&outW[HDIM + h];
        acc += a2.x*w2.x + a2.y*w2.y + a2.z*w2.z + a2.w*w2.w;
    }
#pragma unroll
    for (int off = 16; off; off >>= 1)
        acc += __shfl_down_sync(0xffffffffu, acc, off);
    if (lane == 0) out[w] = 1.f / (1.f + __expf(-(acc + outb[0])));
}

// ---------------------------------------------------------------------------
extern "C" void kernel_launch(void* const* d_in, const int* in_sizes, int n_in,
                              void* d_out, int out_size)
{
    const float* received = (const float*)d_in[0];
    const float* r1_Wih0  = (const float*)d_in[1];
    const float* r1_Whh0  = (const float*)d_in[2];
    const float* r1_bih0  = (const float*)d_in[3];
    const float* r1_bhh0  = (const float*)d_in[4];
    const float* r1_Wih1  = (const float*)d_in[5];
    const float* r1_Whh1  = (const float*)d_in[6];
    const float* r1_bih1  = (const float*)d_in[7];
    const float* r1_bhh1  = (const float*)d_in[8];
    const float* r2_Wih0  = (const float*)d_in[9];
    const float* r2_Whh0  = (const float*)d_in[10];
    const float* r2_bih0  = (const float*)d_in[11];
    const float* r2_bhh0  = (const float*)d_in[12];
    const float* r2_Wih1  = (const float*)d_in[13];
    const float* r2_Whh1  = (const float*)d_in[14];
    const float* r2_bih1  = (const float*)d_in[15];
    const float* r2_bhh1  = (const float*)d_in[16];
    const float* attn_w   = (const float*)d_in[17];
    const float* fc_W     = (const float*)d_in[18];
    const float* fc_b     = (const float*)d_in[19];
    const float* out_W    = (const float*)d_in[20];
    const float* out_b    = (const float*)d_in[21];
    float* out = (float*)d_out;

    float* d_xw1;   cudaGetSymbolAddress((void**)&d_xw1,   g_xw1);
    float* d_h1;    cudaGetSymbolAddress((void**)&d_h1,    g_h1);
    float* d_gout;  cudaGetSymbolAddress((void**)&d_gout,  g_out);
    float* d_cat;   cudaGetSymbolAddress((void**)&d_cat,   g_cat);
    float* d_fused; cudaGetSymbolAddress((void**)&d_fused, g_fused);

    cudaFuncSetAttribute(k_rec<1>, cudaFuncAttributeMaxDynamicSharedMemorySize, REC_SMEM);
    cudaFuncSetAttribute(k_rec<0>, cudaFuncAttributeMaxDynamicSharedMemorySize, REC_SMEM);

    // 1. convert the four 768x256 recurrent matrices to packed bf16 quads
    k_prep<<<(4*64*G3 + 255)/256, 256>>>(r1_Whh0, r2_Whh0, r1_Whh1, r2_Whh1);
    // 2. layer-0 recurrence with fused input projection (both GRUs via grid.y)
    k_rec<1><<<dim3(BATCH/TB, 2), 256, REC_SMEM>>>((const float*)0, received,
                                         r1_Wih0, r2_Wih0, r1_bih0, r2_bih0,
                                         0, r1_bhh0, r2_bhh0, d_h1);
    // 3. layer-1 gate inputs: xw1 = h1 @ Wih1.T + bih1 (both GRUs via grid.z)
    k_gemm<<<dim3(G3/128, BL/128, 2), 256>>>(d_h1, (size_t)BL*HDIM,
                                             r1_Wih1, r2_Wih1, r1_bih1, r2_bih1,
                                             d_xw1, (size_t)BL*G3, G3, HDIM);
    // 4. layer-1 recurrence (pipelined xw)
    k_rec<0><<<dim3(BATCH/TB, 2), 256, REC_SMEM>>>(d_xw1, (const float*)0,
                                         (const float*)0, (const float*)0,
                                         (const float*)0, (const float*)0,
                                         2, r1_bhh1, r2_bhh1, d_gout);
    // 5. attention scalars q,e
    k_qe<<<dim3(BL/8, 2), 256>>>(attn_w);
    // 6. windowed softmax attention + concat
    k_attn<<<dim3(BM95, 2), 256>>>();
    // 7. FC over both branches stacked
    k_gemm<<<dim3(HDIM/128, (2*BM95)/128, 1), 256>>>(d_cat, 0,
                                                     fc_W, fc_W, fc_b, fc_b,
                                                     d_fused, 0, HDIM, 2*HDIM);
    // 8. final projection + sigmoid
    k_final<<<BL/8, 256>>>(out_W, out_b, out);
}

// round 10
// speedup vs baseline: 1.3892x; 1.3892x over previous
#include <cuda_runtime.h>
#include <math.h>

#define BATCH 512
#define LSEQ  100
#define NINPUT 3
#define HDIM  256
#define G3    768
#define DSH   10
#define WINW  5
#define MSEQ  95          // LSEQ - WINW
#define TBR   8           // batch samples per recurrent block
#define NC    8           // fp32 weight slices cached in SMEM per k-half

#define BL    (BATCH*LSEQ)      // 51200
#define BM95  (BATCH*MSEQ)      // 48640

typedef unsigned long long u64;

// ---------------- scratch (static device memory; no allocations) ----------
__device__ float  g_xw1 [2*BL*G3];          // layer-1 gate inputs, per GRU
__device__ float  g_h1  [2*BL*HDIM];        // layer-0 outputs
__device__ float  g_out [2*BL*HDIM];        // layer-1 outputs (out1/out2)
__device__ float  g_q   [2*BL];
__device__ float  g_e   [2*BL];
__device__ float  g_cat [2*BM95*2*HDIM];    // [c, out_shift] concat for FC
__device__ float  g_fused[2*BM95*HDIM];     // FC output
__device__ float4 g_wT4 [4*64*G3];          // transposed Whh, float4 over k
// slots: 0=r1_Whh0 1=r2_Whh0 2=r1_Whh1 3=r2_Whh1

__device__ __forceinline__ float sigf(float x) { return 1.f / (1.f + __expf(-x)); }

__device__ __forceinline__ void fma2(u64& acc, u64 a, u64 b) {
    asm("fma.rn.f32x2 %0, %1, %2, %0;" : "+l"(acc) : "l"(a), "l"(b));
}
__device__ __forceinline__ float sum2(u64 v) {
    float lo, hi; asm("mov.b64 {%0, %1}, %2;" : "=f"(lo), "=f"(hi) : "l"(v));
    return lo + hi;
}

// ---------------- weight transpose: W[g][k] -> wT4[k/4][g] ----------------
__global__ void k_prep(const float* __restrict__ w0, const float* __restrict__ w1,
                       const float* __restrict__ w2, const float* __restrict__ w3)
{
    int idx = blockIdx.x * blockDim.x + threadIdx.x;
    if (idx >= 4 * 64 * G3) return;
    int g  = idx % G3;
    int k4 = (idx / G3) % 64;
    int m  = idx / (G3 * 64);
    const float* W = (m == 0) ? w0 : (m == 1) ? w1 : (m == 2) ? w2 : w3;
    const float* p = W + g * HDIM + 4 * k4;
    g_wT4[idx] = make_float4(p[0], p[1], p[2], p[3]);
}

// ---------------- GRU recurrence (R6 best: 512 thr, k-split, fp32) ---------
template<int FUSE>
__global__ void __launch_bounds__(512, 1)
k_rec(const float* __restrict__ xw_base, const float* __restrict__ xin,
      const float* __restrict__ Wih_0, const float* __restrict__ Wih_1,
      const float* __restrict__ bih_0, const float* __restrict__ bih_1,
      int wslot,
      const float* __restrict__ bhh_0, const float* __restrict__ bhh_1,
      float* __restrict__ hout_base)
{
    int r  = blockIdx.y;
    int tid = threadIdx.x;
    int j  = tid & 255;
    int kh = tid >> 8;
    int b0 = blockIdx.x * TBR;
    const float*  bhh  = r ? bhh_1 : bhh_0;
    const float4* Wbase = g_wT4 + (size_t)(wslot + r) * (64 * G3);
    const float4* W    = Wbase + kh * 32 * G3;
    const float4* Wg   = W + NC * G3;
    const float*  xw   = xw_base ? (xw_base + (size_t)r * BL * G3) : (const float*)0;
    float*        hout = hout_base + (size_t)r * BL * HDIM;

    extern __shared__ __align__(16) char dsm[];
    float*  hs = (float*)dsm;
    float*  ps = hs + TBR * HDIM;
    float4* Wc = (float4*)(ps + 2 * 3 * 4 * HDIM);
    const float4* Wch = Wc + kh * NC * G3;

    for (int idx = tid; idx < 2 * NC * G3; idx += 512) {
        int half = idx / (NC * G3);
        int rem  = idx % (NC * G3);
        Wc[idx] = Wbase[half * 32 * G3 + rem];
    }

    int bown = kh * 4;
    float* ps_w       = ps + kh * 3 * 4 * HDIM;
    const float* ps_r = ps + (1 - kh) * 3 * 4 * HDIM;

    float wx[9], bx[3];
    if (FUSE) {
        const float* Wih = r ? Wih_1 : Wih_0;
        const float* bih = r ? bih_1 : bih_0;
#pragma unroll
        for (int g = 0; g < 3; g++) {
            wx[g*3+0] = Wih[(j + g*HDIM)*3 + 0];
            wx[g*3+1] = Wih[(j + g*HDIM)*3 + 1];
            wx[g*3+2] = Wih[(j + g*HDIM)*3 + 2];
            bx[g]     = bih[j + g*HDIM];
        }
    }

#pragma unroll
    for (int i = 0; i < 4; i++) hs[(bown + i) * HDIM + j] = 0.f;
    float bhr = bhh[j], bhz = bhh[j + HDIM], bhn = bhh[j + 2*HDIM];

    float xg[12];
    if (FUSE) {
#pragma unroll
        for (int i = 0; i < 4; i++) {
            size_t base = ((size_t)(b0 + bown + i) * LSEQ + 0) * NINPUT;
            xg[i*3+0] = xin[base+0]; xg[i*3+1] = xin[base+1]; xg[i*3+2] = xin[base+2];
        }
    } else {
#pragma unroll
        for (int i = 0; i < 4; i++) {
            size_t base = ((size_t)(b0 + bown + i) * LSEQ + 0) * G3;
            xg[i*3+0] = xw[base + j];
            xg[i*3+1] = xw[base + HDIM + j];
            xg[i*3+2] = xw[base + 2*HDIM + j];
        }
    }
    __syncthreads();

    const float* hb_own = hs + bown * HDIM       + kh * 128;
    const float* hb_oth = hs + (4 - bown) * HDIM + kh * 128;

    for (int t = 0; t < LSEQ; t++) {
        u64 arO[4], azO[4], anO[4], arX[4], azX[4], anX[4];
#pragma unroll
        for (int i = 0; i < 4; i++) {
            arO[i]=0ull; azO[i]=0ull; anO[i]=0ull;
            arX[i]=0ull; azX[i]=0ull; anX[i]=0ull;
        }

#pragma unroll 4
        for (int kk = 0; kk < NC; kk++) {
            ulonglong2 w0 = *(const ulonglong2*)&Wch[kk*G3 + j];
            ulonglong2 w1 = *(const ulonglong2*)&Wch[kk*G3 + HDIM + j];
            ulonglong2 w2 = *(const ulonglong2*)&Wch[kk*G3 + 2*HDIM + j];
#pragma unroll
            for (int i = 0; i < 4; i++) {
                ulonglong2 h2 = *(const ulonglong2*)&hb_own[i*HDIM + kk*4];
                fma2(arO[i], w0.x, h2.x); fma2(arO[i], w0.y, h2.y);
                fma2(azO[i], w1.x, h2.x); fma2(azO[i], w1.y, h2.y);
                fma2(anO[i], w2.x, h2.x); fma2(anO[i], w2.y, h2.y);
            }
#pragma unroll
            for (int i = 0; i < 4; i++) {
                ulonglong2 h2 = *(const ulonglong2*)&hb_oth[i*HDIM + kk*4];
                fma2(arX[i], w0.x, h2.x); fma2(arX[i], w0.y, h2.y);
                fma2(azX[i], w1.x, h2.x); fma2(azX[i], w1.y, h2.y);
                fma2(anX[i], w2.x, h2.x); fma2(anX[i], w2.y, h2.y);
            }
        }

        {
            ulonglong2 p0[2], p1[2], p2[2];
#pragma unroll
            for (int d = 0; d < 2; d++) {
                p0[d] = *(const ulonglong2*)&Wg[d*G3 + j];
                p1[d] = *(const ulonglong2*)&Wg[d*G3 + HDIM + j];
                p2[d] = *(const ulonglong2*)&Wg[d*G3 + 2*HDIM + j];
            }
#pragma unroll
            for (int kk = NC; kk < 32; kk++) {
                int s = kk & 1;
                ulonglong2 w0 = p0[s], w1 = p1[s], w2 = p2[s];
                if (kk + 2 < 32) {
                    p0[s] = *(const ulonglong2*)&Wg[(kk+2-NC)*G3 + j];
                    p1[s] = *(const ulonglong2*)&Wg[(kk+2-NC)*G3 + HDIM + j];
                    p2[s] = *(const ulonglong2*)&Wg[(kk+2-NC)*G3 + 2*HDIM + j];
                }
#pragma unroll
                for (int i = 0; i < 4; i++) {
                    ulonglong2 h2 = *(const ulonglong2*)&hb_own[i*HDIM + kk*4];
                    fma2(arO[i], w0.x, h2.x); fma2(arO[i], w0.y, h2.y);
                    fma2(azO[i], w1.x, h2.x); fma2(azO[i], w1.y, h2.y);
                    fma2(anO[i], w2.x, h2.x); fma2(anO[i], w2.y, h2.y);
                }
#pragma unroll
                for (int i = 0; i < 4; i++) {
                    ulonglong2 h2 = *(const ulonglong2*)&hb_oth[i*HDIM + kk*4];
                    fma2(arX[i], w0.x, h2.x); fma2(arX[i], w0.y, h2.y);
                    fma2(azX[i], w1.x, h2.x); fma2(azX[i], w1.y, h2.y);
                    fma2(anX[i], w2.x, h2.x); fma2(anX[i], w2.y, h2.y);
                }
            }
        }

#pragma unroll
        for (int i = 0; i < 4; i++) {
            ps_w[0*4*HDIM + i*HDIM + j] = sum2(arX[i]);
            ps_w[1*4*HDIM + i*HDIM + j] = sum2(azX[i]);
            ps_w[2*4*HDIM + i*HDIM + j] = sum2(anX[i]);
        }
        __syncthreads();

#pragma unroll
        for (int i = 0; i < 4; i++) {
            float gr, gz, gn;
            if (FUSE) {
                float x0 = xg[i*3+0], x1 = xg[i*3+1], x2 = xg[i*3+2];
                gr = bx[0] + x0*wx[0] + x1*wx[1] + x2*wx[2];
                gz = bx[1] + x0*wx[3] + x1*wx[4] + x2*wx[5];
                gn = bx[2] + x0*wx[6] + x1*wx[7] + x2*wx[8];
            } else {
                gr = xg[i*3+0]; gz = xg[i*3+1]; gn = xg[i*3+2];
            }
            float rg = sigf(gr + sum2(arO[i]) + ps_r[0*4*HDIM + i*HDIM + j] + bhr);
            float zg = sigf(gz + sum2(azO[i]) + ps_r[1*4*HDIM + i*HDIM + j] + bhz);
            float ng = tanhf(gn + rg * (sum2(anO[i]) + ps_r[2*4*HDIM + i*HDIM + j] + bhn));
            float hn = (1.f - zg) * ng + zg * hs[(bown + i)*HDIM + j];
            hs[(bown + i)*HDIM + j] = hn;
            hout[((size_t)(b0 + bown + i) * LSEQ + t) * HDIM + j] = hn;
        }
        if (t + 1 < LSEQ) {
            if (FUSE) {
#pragma unroll
                for (int i = 0; i < 4; i++) {
                    size_t base = ((size_t)(b0 + bown + i) * LSEQ + (t+1)) * NINPUT;
                    xg[i*3+0] = xin[base+0]; xg[i*3+1] = xin[base+1]; xg[i*3+2] = xin[base+2];
                }
            } else {
#pragma unroll
                for (int i = 0; i < 4; i++) {
                    size_t base = ((size_t)(b0 + bown + i) * LSEQ + (t+1)) * G3;
                    xg[i*3+0] = xw[base + j];
                    xg[i*3+1] = xw[base + HDIM + j];
                    xg[i*3+2] = xw[base + 2*HDIM + j];
                }
            }
        }
        __syncthreads();
    }
}

#define REC_SMEM ((TBR*HDIM + 2*3*4*HDIM) * 4 + 2*NC*G3*16)

// ==================== mma.sync bf16 GEMM (sm_80+ path) ======================
// C[M,Ntot] = A[M,K] @ B[Ntot,K]^T + bias.
// CTA tile 128M x 128N, BK=64, 8 warps (4m x 2n), warp tile 32 x 64.
// fp32 gmem -> bf16 SMEM (padded stride 72 halves), ldmatrix + m16n8k16.
// M%128==0, Ntot%128==0, K%64==0.
#define LDSTR 72                      // SMEM halves per row (64 + 8 pad)
#define MM_SMEM (2 * 128 * LDSTR * 2) // two bf16 tiles

__device__ __forceinline__ unsigned pack_bf(float lo, float hi) {
    unsigned r; asm("cvt.rn.bf16x2.f32 %0, %1, %2;" : "=r"(r) : "f"(hi), "f"(lo));
    return r;
}

__global__ void __launch_bounds__(256)
k_mma(const float* __restrict__ A, size_t strideAz,
      const float* __restrict__ B0, const float* __restrict__ B1,
      const float* __restrict__ bias0, const float* __restrict__ bias1,
      float* __restrict__ C, size_t strideCz, int Ntot, int K)
{
    extern __shared__ __align__(16) char smm[];
    unsigned sAu;
    asm("{ .reg .u64 t; cvta.to.shared.u64 t, %1; cvt.u32.u64 %0, t; }"
        : "=r"(sAu) : "l"(smm));
    unsigned sBu = sAu + 128 * LDSTR * 2;

    int z = blockIdx.z;
    const float* Az   = A + (size_t)z * strideAz;
    const float* Bw   = z ? B1 : B0;
    const float* bias = z ? bias1 : bias0;
    float*       Cz   = C + (size_t)z * strideCz;

    int tid = threadIdx.x;
    int wid = tid >> 5, lane = tid & 31;
    int wm = wid & 3, wn = wid >> 2;        // warp grid 4m x 2n
    int bm = blockIdx.y * 128, bn = blockIdx.x * 128;

    float acc[2][8][4];
#pragma unroll
    for (int mt = 0; mt < 2; mt++)
#pragma unroll
        for (int nt = 0; nt < 8; nt++)
#pragma unroll
            for (int q = 0; q < 4; q++) acc[mt][nt][q] = 0.f;

    int lrow = tid >> 1, lh = tid & 1;      // load mapping: 2 thr/row, 32 f32 each

    for (int kc = 0; kc < K; kc += 64) {
        __syncthreads();
        // A tile: 128 x 64 fp32 -> bf16
#pragma unroll
        for (int i = 0; i < 8; i++) {
            float4 v = *(const float4*)&Az[(size_t)(bm + lrow) * K + kc + lh*32 + i*4];
            unsigned lo = pack_bf(v.x, v.y), hi = pack_bf(v.z, v.w);
            u64 pk; asm("mov.b64 %0, {%1, %2};" : "=l"(pk) : "r"(lo), "r"(hi));
            unsigned ad = sAu + 2u * (lrow * LDSTR + lh*32 + i*4);
            asm volatile("st.shared.b64 [%0], %1;" :: "r"(ad), "l"(pk) : "memory");
        }
        // B tile: 128 x 64 fp32 -> bf16
#pragma unroll
        for (int i = 0; i < 8; i++) {
            float4 v = *(const float4*)&Bw[(size_t)(bn + lrow) * K + kc + lh*32 + i*4];
            unsigned lo = pack_bf(v.x, v.y), hi = pack_bf(v.z, v.w);
            u64 pk; asm("mov.b64 %0, {%1, %2};" : "=l"(pk) : "r"(lo), "r"(hi));
            unsigned ad = sBu + 2u * (lrow * LDSTR + lh*32 + i*4);
            asm volatile("st.shared.b64 [%0], %1;" :: "r"(ad), "l"(pk) : "memory");
        }
        __syncthreads();

#pragma unroll
        for (int ks = 0; ks < 4; ks++) {
            unsigned af[2][4];
#pragma unroll
            for (int mt = 0; mt < 2; mt++) {
                unsigned ad = sAu + 2u * ((wm*32 + mt*16 + (lane & 15)) * LDSTR
                                          + ks*16 + (lane >> 4) * 8);
                asm volatile(
                    "ldmatrix.sync.aligned.m8n8.x4.shared.b16 {%0,%1,%2,%3}, [%4];"
                    : "=r"(af[mt][0]), "=r"(af[mt][1]), "=r"(af[mt][2]), "=r"(af[mt][3])
                    : "r"(ad));
            }
#pragma unroll
            for (int nt = 0; nt < 8; nt++) {
                unsigned bd = sBu + 2u * ((wn*64 + nt*8 + (lane & 7)) * LDSTR
                                          + ks*16 + ((lane >> 3) & 1) * 8);
                unsigned bf0, bf1;
                asm volatile(
                    "ldmatrix.sync.aligned.m8n8.x2.shared.b16 {%0,%1}, [%2];"
                    : "=r"(bf0), "=r"(bf1) : "r"(bd));
#pragma unroll
                for (int mt = 0; mt < 2; mt++) {
                    asm volatile(
                        "mma.sync.aligned.m16n8k16.row.col.f32.bf16.bf16.f32 "
                        "{%0,%1,%2,%3}, {%4,%5,%6,%7}, {%8,%9}, {%0,%1,%2,%3};"
                        : "+f"(acc[mt][nt][0]), "+f"(acc[mt][nt][1]),
                          "+f"(acc[mt][nt][2]), "+f"(acc[mt][nt][3])
                        : "r"(af[mt][0]), "r"(af[mt][1]), "r"(af[mt][2]), "r"(af[mt][3]),
                          "r"(bf0), "r"(bf1));
                }
            }
        }
    }

    // epilogue: add bias, store
    int row0 = bm + wm*32;
    int col0 = bn + wn*64;
#pragma unroll
    for (int mt = 0; mt < 2; mt++) {
        int r0 = row0 + mt*16 + (lane >> 2);
#pragma unroll
        for (int nt = 0; nt < 8; nt++) {
            int c = col0 + nt*8 + (lane & 3) * 2;
            float b0v = bias[c], b1v = bias[c + 1];
            float2 v0 = make_float2(acc[mt][nt][0] + b0v, acc[mt][nt][1] + b1v);
            float2 v1 = make_float2(acc[mt][nt][2] + b0v, acc[mt][nt][3] + b1v);
            *(float2*)&Cz[(size_t)r0 * Ntot + c]       = v0;
            *(float2*)&Cz[(size_t)(r0 + 8) * Ntot + c] = v1;
        }
    }
}

// ---------------- q = out@aw[:H], e = out@aw[H:] (warp per (b,l)) ----------
__global__ void k_qe(const float* __restrict__ attn_w)
{
    int r    = blockIdx.y;
    int w    = blockIdx.x * 8 + (threadIdx.x >> 5);
    int lane = threadIdx.x & 31;
    const float* o = g_out + ((size_t)r * BL + w) * HDIM;
    float q = 0.f, e = 0.f;
#pragma unroll
    for (int h = lane * 8; h < lane * 8 + 8; h += 4) {
        float4 ov = *(const float4*)&o[h];
        float4 a1 = *(const float4*)&attn_w[h];
        float4 a2 = *(const float4*)&attn_w[HDIM + h];
        q += ov.x*a1.x + ov.y*a1.y + ov.z*a1.z + ov.w*a1.w;
        e += ov.x*a2.x + ov.y*a2.y + ov.z*a2.z + ov.w*a2.w;
    }
#pragma unroll
    for (int off = 16; off; off >>= 1) {
        q += __shfl_down_sync(0xffffffffu, q, off);
        e += __shfl_down_sync(0xffffffffu, e, off);
    }
    if (lane == 0) { g_q[r * BL + w] = q; g_e[r * BL + w] = e; }
}

// ---------------- windowed attention + concat for FC ----------------------
__global__ void k_attn()
{
    int r    = blockIdx.y;
    int bl95 = blockIdx.x;
    int b    = bl95 / MSEQ, l = bl95 % MSEQ;
    int h    = threadIdx.x;

    const float* qrow = g_q + r * BL + b * LSEQ;
    const float* erow = g_e + r * BL + b * LSEQ;
    float qv = qrow[l + WINW];
    float s[WINW];
    float mx = -1e30f;
#pragma unroll
    for (int k = 0; k < WINW; k++) { s[k] = qv + erow[l + k]; mx = fmaxf(mx, s[k]); }
    float sum = 0.f;
#pragma unroll
    for (int k = 0; k < WINW; k++) { s[k] = __expf(s[k] - mx); sum += s[k]; }
    float inv = 1.f / sum;

    const float* o = g_out + ((size_t)r * BL + b * LSEQ + l) * HDIM;
    float c = 0.f;
#pragma unroll
    for (int k = 0; k < WINW; k++) c += s[k] * inv * o[k * HDIM + h];

    size_t m = (size_t)r * BM95 + bl95;
    g_cat[m * (2*HDIM) + h]        = c;
    g_cat[m * (2*HDIM) + HDIM + h] = o[WINW * HDIM + h];
}

// ---------------- final head: concat(rnn1[b,l], rnn2[b,min(l+D,99)]) ------
__global__ void k_final(const float* __restrict__ outW, const float* __restrict__ outb,
                        float* __restrict__ out)
{
    int w    = blockIdx.x * 8 + (threadIdx.x >> 5);
    int lane = threadIdx.x & 31;
    int b = w / LSEQ, l = w % LSEQ;

    const float* A1 = (l < WINW)
        ? (g_out   + ((size_t)(b * LSEQ + l)) * HDIM)
        : (g_fused + ((size_t)(b * MSEQ + l - WINW)) * HDIM);
    int lidx = min(l + DSH, LSEQ - 1);
    const float* A2 = (lidx < WINW)
        ? (g_out   + ((size_t)BL + b * LSEQ + lidx) * HDIM)
        : (g_fused + ((size_t)BM95 + b * MSEQ + lidx - WINW) * HDIM);

    float acc = 0.f;
#pragma unroll
    for (int h = lane * 8; h < lane * 8 + 8; h += 4) {
        float4 a  = *(const float4*)&A1[h];
        float4 w1 = *(const float4*)&outW[h];
        acc += a.x*w1.x + a.y*w1.y + a.z*w1.z + a.w*w1.w;
        float4 a2 = *(const float4*)&A2[h];
        float4 w2 = *(const float4*)&outW[HDIM + h];
        acc += a2.x*w2.x + a2.y*w2.y + a2.z*w2.z + a2.w*w2.w;
    }
#pragma unroll
    for (int off = 16; off; off >>= 1)
        acc += __shfl_down_sync(0xffffffffu, acc, off);
    if (lane == 0) out[w] = 1.f / (1.f + __expf(-(acc + outb[0])));
}

// ---------------------------------------------------------------------------
extern "C" void kernel_launch(void* const* d_in, const int* in_sizes, int n_in,
                              void* d_out, int out_size)
{
    const float* received = (const float*)d_in[0];
    const float* r1_Wih0  = (const float*)d_in[1];
    const float* r1_Whh0  = (const float*)d_in[2];
    const float* r1_bih0  = (const float*)d_in[3];
    const float* r1_bhh0  = (const float*)d_in[4];
    const float* r1_Wih1  = (const float*)d_in[5];
    const float* r1_Whh1  = (const float*)d_in[6];
    const float* r1_bih1  = (const float*)d_in[7];
    const float* r1_bhh1  = (const float*)d_in[8];
    const float* r2_Wih0  = (const float*)d_in[9];
    const float* r2_Whh0  = (const float*)d_in[10];
    const float* r2_bih0  = (const float*)d_in[11];
    const float* r2_bhh0  = (const float*)d_in[12];
    const float* r2_Wih1  = (const float*)d_in[13];
    const float* r2_Whh1  = (const float*)d_in[14];
    const float* r2_bih1  = (const float*)d_in[15];
    const float* r2_bhh1  = (const float*)d_in[16];
    const float* attn_w   = (const float*)d_in[17];
    const float* fc_W     = (const float*)d_in[18];
    const float* fc_b     = (const float*)d_in[19];
    const float* out_W    = (const float*)d_in[20];
    const float* out_b    = (const float*)d_in[21];
    float* out = (float*)d_out;

    float* d_xw1;   cudaGetSymbolAddress((void**)&d_xw1,   g_xw1);
    float* d_h1;    cudaGetSymbolAddress((void**)&d_h1,    g_h1);
    float* d_gout;  cudaGetSymbolAddress((void**)&d_gout,  g_out);
    float* d_cat;   cudaGetSymbolAddress((void**)&d_cat,   g_cat);
    float* d_fused; cudaGetSymbolAddress((void**)&d_fused, g_fused);

    cudaFuncSetAttribute(k_rec<1>, cudaFuncAttributeMaxDynamicSharedMemorySize, REC_SMEM);
    cudaFuncSetAttribute(k_rec<0>, cudaFuncAttributeMaxDynamicSharedMemorySize, REC_SMEM);
    cudaFuncSetAttribute(k_mma,    cudaFuncAttributeMaxDynamicSharedMemorySize, MM_SMEM);

    // 1. transpose the four 768x256 recurrent matrices (fp32)
    k_prep<<<(4*64*G3 + 255)/256, 256>>>(r1_Whh0, r2_Whh0, r1_Whh1, r2_Whh1);
    // 2. layer-0 recurrence with fused input projection
    k_rec<1><<<dim3(BATCH/TBR, 2), 512, REC_SMEM>>>((const float*)0, received,
                                         r1_Wih0, r2_Wih0, r1_bih0, r2_bih0,
                                         0, r1_bhh0, r2_bhh0, d_h1);
    // 3. xw1 = h1 @ Wih1.T + bih1 — bf16 mma.sync GEMM
    k_mma<<<dim3(G3/128, BL/128, 2), 256, MM_SMEM>>>(
        d_h1, (size_t)BL*HDIM, r1_Wih1, r2_Wih1, r1_bih1, r2_bih1,
        d_xw1, (size_t)BL*G3, G3, HDIM);
    // 4. layer-1 recurrence
    k_rec<0><<<dim3(BATCH/TBR, 2), 512, REC_SMEM>>>(d_xw1, (const float*)0,
                                         (const float*)0, (const float*)0,
                                         (const float*)0, (const float*)0,
                                         2, r1_bhh1, r2_bhh1, d_gout);
    // 5. attention scalars q,e
    k_qe<<<dim3(BL/8, 2), 256>>>(attn_w);
    // 6. windowed softmax attention + concat
    k_attn<<<dim3(BM95, 2), 256>>>();
    // 7. FC — bf16 mma.sync GEMM
    k_mma<<<dim3(HDIM/128, (2*BM95)/128, 1), 256, MM_SMEM>>>(
        d_cat, 0, fc_W, fc_W, fc_b, fc_b,
        d_fused, 0, HDIM, 2*HDIM);
    // 8. final projection + sigmoid
    k_final<<<BL/8, 256>>>(out_W, out_b, out);
}